// round 15
// baseline (speedup 1.0000x reference)
#include <cuda_runtime.h>
#include <cuda_fp16.h>
#include <cstdint>
#include <cstddef>
#include <cstring>

// Problem constants (fixed-shape problem)
#define N0c 200000
#define N1c 100000
#define N2c 50000
#define E1c 1600000
#define E2c 800000
#define FIN 128
#define FHID 256
#define FOUT 128

// count layout: [0,N0) out1 | [N0,+N1) in1 | [+N1) out2 | [+N2) in2
#define OFF_OUT1 0
#define OFF_IN1  200000
#define OFF_OUT2 300000
#define OFF_IN2  400000
#define DEG_TOT  450000

#define NB1 ((N1c + 255) / 256)   // 391
#define NB2 ((N2c + 255) / 256)   // 196
#define NBT (NB1 + NB2)           // 587
#define CVT_BLOCKS ((N0c * 16 + 255) / 256)   // 12500

// Scratch (no allocations allowed)
__device__ int    g_icnt[DEG_TOT];
__device__ int    g_off1[N1c + 1];
__device__ int    g_cur1[N1c];
__device__ int    g_off2[N2c + 1];
__device__ int    g_cur2[N2c];
__device__ int    g_csr1[E1c];
__device__ int    g_csr2[E2c];
__device__ int    g_bsum[1024];
__device__ __half g_w1h[FHID * FIN];            // W1^T fp16 [n][k]
__device__ __half g_w2h[FOUT * FHID];           // W2^T fp16 [n][k]
__device__ uint2  g_xh[(size_t)N0c * 32];       // fp16 pre-scaled X, 51.2 MB
__device__ __half g_y16[(size_t)N1c * FOUT];    // 25.6 MB

__device__ __forceinline__ uint32_t h2_as_u32(__half2 h) {
    uint32_t u; memcpy(&u, &h, 4); return u;
}
__device__ __forceinline__ __half2 u32_as_h2(uint32_t u) {
    __half2 h; memcpy(&h, &u, 4); return h;
}
__device__ __forceinline__ float inv_sqrt_cnt(int c) {
    return rsqrtf((float)max(c, 1));
}

// ---------------------------------------------------------------------------
__global__ void prep_kernel(const float* __restrict__ W1, const float* __restrict__ W2) {
    int i = blockIdx.x * blockDim.x + threadIdx.x;
    if (i < DEG_TOT / 4) ((int4*)g_icnt)[i] = make_int4(0, 0, 0, 0);
    if (i < DEG_TOT - (DEG_TOT / 4) * 4) g_icnt[(DEG_TOT / 4) * 4 + i] = 0;
    if (i < FIN * FHID) {                       // W1 [k=FIN][n=FHID] -> [n][k]
        int k = i / FHID, n = i % FHID;
        g_w1h[n * FIN + k] = __float2half(W1[i]);
    }
    if (i < FHID * FOUT) {                      // W2 [k=FHID][n=FOUT] -> [n][k]
        int k = i / FOUT, n = i % FOUT;
        g_w2h[n * FHID + k] = __float2half(W2[i]);
    }
}

__global__ void degree_kernel(const int* __restrict__ s1, const int* __restrict__ d1,
                              const int* __restrict__ s2, const int* __restrict__ d2) {
    int i = blockIdx.x * blockDim.x + threadIdx.x;
    if (i < E1c) {
        atomicAdd(&g_icnt[OFF_OUT1 + s1[i]], 1);
        atomicAdd(&g_icnt[OFF_IN1 + d1[i]], 1);
    }
    if (i < E2c) {
        atomicAdd(&g_icnt[OFF_OUT2 + s2[i]], 1);
        atomicAdd(&g_icnt[OFF_IN2 + d2[i]], 1);
    }
}

// Merged: blocks [0, NBT) = scan pass1; blocks [NBT, ...) = X -> fp16 convert.
__global__ __launch_bounds__(256) void convscan_kernel(const float* __restrict__ X) {
    int b = blockIdx.x, tid = threadIdx.x;
    if (b < NBT) {
        __shared__ int sh[256];
        int v = 0;
        if (b < NB1) {
            int idx = b * 256 + tid;
            if (idx < N1c) v = g_icnt[OFF_IN1 + idx];
        } else {
            int idx = (b - NB1) * 256 + tid;
            if (idx < N2c) v = g_icnt[OFF_IN2 + idx];
        }
        sh[tid] = v;
        __syncthreads();
        for (int s = 128; s > 0; s >>= 1) {
            if (tid < s) sh[tid] += sh[tid + s];
            __syncthreads();
        }
        if (tid == 0) g_bsum[b] = sh[0];
        return;
    }
    int i = (b - NBT) * 256 + tid;
    const int HALF = N0c * 16;
    if (i >= HALF) return;
#pragma unroll
    for (int j = 0; j < 2; j++) {
        int idx = i + j * HALF;
        int row = idx >> 5;
        float c = inv_sqrt_cnt(g_icnt[OFF_OUT1 + row]);
        float4 v = ((const float4*)X)[idx];
        uint2 o;
        o.x = h2_as_u32(__floats2half2_rn(v.x * c, v.y * c));
        o.y = h2_as_u32(__floats2half2_rn(v.z * c, v.w * c));
        g_xh[idx] = o;
    }
}

// Fused pass2+3: per-block prefix over g_bsum + local scan + CSR offsets.
__global__ __launch_bounds__(256) void scan_pass23() {
    __shared__ int sh[256];
    __shared__ int shr[256];
    int b = blockIdx.x, tid = threadIdx.x;
    bool g1 = (b < NB1);
    int seg_start = g1 ? 0 : NB1;

    int acc = 0;
    for (int p = seg_start + tid; p < b; p += 256) acc += g_bsum[p];
    shr[tid] = acc;
    __syncthreads();
    for (int s = 128; s > 0; s >>= 1) {
        if (tid < s) shr[tid] += shr[tid + s];
        __syncthreads();
    }
    int block_off = shr[0];

    int idx, v = 0;
    if (g1) {
        idx = b * 256 + tid;
        if (idx < N1c) v = g_icnt[OFF_IN1 + idx];
    } else {
        idx = (b - NB1) * 256 + tid;
        if (idx < N2c) v = g_icnt[OFF_IN2 + idx];
    }
    sh[tid] = v;
    __syncthreads();
    for (int s = 1; s < 256; s <<= 1) {
        int a = (tid >= s) ? sh[tid - s] : 0;
        __syncthreads();
        sh[tid] += a;
        __syncthreads();
    }
    int excl = block_off + sh[tid] - v;
    if (g1) {
        if (idx < N1c) { g_off1[idx] = excl; g_cur1[idx] = excl; }
    } else {
        if (idx < N2c) { g_off2[idx] = excl; g_cur2[idx] = excl; }
    }
    if (b == 0 && tid == 0) { g_off1[N1c] = E1c; g_off2[N2c] = E2c; }
}

// --- CSR fill (counting-sort edges by dst) ----------------------------------
__global__ void fill_kernel(const int* __restrict__ s1, const int* __restrict__ d1,
                            const int* __restrict__ s2, const int* __restrict__ d2) {
    int i = blockIdx.x * blockDim.x + threadIdx.x;
    if (i < E1c) {
        int p = atomicAdd(&g_cur1[d1[i]], 1);
        g_csr1[p] = s1[i];
    }
    if (i < E2c) {
        int p = atomicAdd(&g_cur2[d2[i]], 1);
        g_csr2[p] = s2[i];
    }
}

// --- Layer-2 aggregate (fp16 gather) + fused scale/bias/relu ----------------
__global__ __launch_bounds__(256) void agg2_kernel(const float* __restrict__ bias,
                                                   float* __restrict__ OUT) {
    int w = (blockIdx.x * blockDim.x + threadIdx.x) >> 5;
    if (w >= N2c) return;
    int lane = threadIdx.x & 31;
    int i = g_off2[w], end = g_off2[w + 1];
    float4 acc = make_float4(0.f, 0.f, 0.f, 0.f);
    const uint2* Y2 = (const uint2*)g_y16;
    for (; i + 1 < end; i += 2) {
        int s0 = g_csr2[i], s1 = g_csr2[i + 1];
        uint2 u0 = Y2[(size_t)s0 * 32 + lane];
        uint2 u1 = Y2[(size_t)s1 * 32 + lane];
        float2 a0 = __half22float2(u32_as_h2(u0.x));
        float2 b0 = __half22float2(u32_as_h2(u0.y));
        float2 a1 = __half22float2(u32_as_h2(u1.x));
        float2 b1 = __half22float2(u32_as_h2(u1.y));
        acc.x += a0.x + a1.x; acc.y += a0.y + a1.y;
        acc.z += b0.x + b1.x; acc.w += b0.y + b1.y;
    }
    if (i < end) {
        int s0 = g_csr2[i];
        uint2 u0 = Y2[(size_t)s0 * 32 + lane];
        float2 a0 = __half22float2(u32_as_h2(u0.x));
        float2 b0 = __half22float2(u32_as_h2(u0.y));
        acc.x += a0.x; acc.y += a0.y; acc.z += b0.x; acc.w += b0.y;
    }
    float s = inv_sqrt_cnt(g_icnt[OFF_IN2 + w]);
    float4 b = ((const float4*)bias)[lane];
    acc.x = fmaxf(fmaf(acc.x, s, b.x), 0.f);
    acc.y = fmaxf(fmaf(acc.y, s, b.y), 0.f);
    acc.z = fmaxf(fmaf(acc.z, s, b.z), 0.f);
    acc.w = fmaxf(fmaf(acc.w, s, b.w), 0.f);
    ((float4*)OUT)[(size_t)w * 32 + lane] = acc;
}

// ---------------------------------------------------------------------------
// Fused GCN layer kernel v3: per 128-row CTA
//   Gather: warps CSR-gather their rows from g_xh -> fp16 into Hs[.][64..127]
//           (identical values/layout to the old agg1 -> a16 -> cp.async path)
//   Stage A (x2 n-passes): Hs[128][256] fp16 = relu(rs1*agg1@W1 + b1)
//   Stage B: y[128][128] fp16 = rs2 * Hs@W2
// ---------------------------------------------------------------------------
#define TS 20                 // B tile row stride in uint32 (16 data + 4 pad)
#define HS2 132               // Hs row stride in uint32 (128 data + 4 pad)
#define BS_E (128 * TS)
#define HS_E (128 * HS2)
#define SMEM_FUSED ((HS_E + 2 * BS_E) * 4)

__device__ __forceinline__ uint32_t smem_u32(const void* p) {
    return (uint32_t)__cvta_generic_to_shared(p);
}
__device__ __forceinline__ void cp16(uint32_t dst, const void* src, int src_bytes) {
    asm volatile("cp.async.cg.shared.global [%0], [%1], 16, %2;"
                 :: "r"(dst), "l"(src), "r"(src_bytes));
}
__device__ __forceinline__ void mma_f16(float c[4], const uint32_t a[4], const uint32_t b[2]) {
    asm volatile(
        "mma.sync.aligned.m16n8k16.row.col.f32.f16.f16.f32 "
        "{%0,%1,%2,%3}, {%4,%5,%6,%7}, {%8,%9}, {%0,%1,%2,%3};"
        : "+f"(c[0]), "+f"(c[1]), "+f"(c[2]), "+f"(c[3])
        : "r"(a[0]), "r"(a[1]), "r"(a[2]), "r"(a[3]), "r"(b[0]), "r"(b[1]));
}
__device__ __forceinline__ void ldsm4(uint32_t& r0, uint32_t& r1, uint32_t& r2,
                                      uint32_t& r3, uint32_t addr) {
    asm volatile("ldmatrix.sync.aligned.m8n8.x4.shared.b16 {%0,%1,%2,%3}, [%4];"
                 : "=r"(r0), "=r"(r1), "=r"(r2), "=r"(r3) : "r"(addr));
}

__global__ __launch_bounds__(256) void fused_layer(
    __half* __restrict__ Y,           // [M,128] fp16
    const float* __restrict__ b1, int M)
{
    extern __shared__ uint32_t sm[];
    uint32_t (*Hs)[HS2]      = (uint32_t (*)[HS2])sm;
    uint32_t (*Bst)[128][TS] = (uint32_t (*)[128][TS])(sm + HS_E);

    int tid = threadIdx.x;
    int wid = tid >> 5, lane = tid & 31;
    int g = lane >> 2, tig = lane & 3;
    int warp_m = (wid & 3) * 32;
    int warp_n = (wid >> 2) * 64;
    int rowBase = blockIdx.x * 128;

    // ldmatrix source indexing
    int j = lane >> 3, lr = lane & 7;
    int a_rowadd = (j & 1) * 8;
    int a_kadd   = (j >> 1) * 4;
    int b_nadd   = (j >> 1) * 8;
    int b_kadd   = (j & 1) * 4;

    auto loadB = [&](const __half* Wt, int ldk, int nb, int t, int buf) {
#pragma unroll
        for (int i = 0; i < 2; i++) {
            int gI = tid + 256 * i;
            int brow = gI >> 2, b16 = gI & 3;
            cp16(smem_u32(&Bst[buf][brow][b16 * 4]),
                 Wt + ((size_t)(nb + brow) * ldk + t * 32 + b16 * 8), 16);
        }
    };

    // B tile 0 in flight while we gather
    loadB(g_w1h, FIN, 0, 0, 0);
    asm volatile("cp.async.commit_group;" ::: "memory");

    // ---- CSR gather: 16 rows per warp -> Hs[r][64 + 2*lane(+1)] -----------
#pragma unroll 1
    for (int rr = 0; rr < 16; rr++) {
        int r = wid * 16 + rr;
        int row = rowBase + r;
        uint2 o = make_uint2(0u, 0u);
        if (row < M) {
            int i = g_off1[row], end = g_off1[row + 1];
            float4 acc = make_float4(0.f, 0.f, 0.f, 0.f);
            for (; i + 1 < end; i += 2) {
                int s0 = g_csr1[i], s1 = g_csr1[i + 1];
                uint2 u0 = g_xh[(size_t)s0 * 32 + lane];
                uint2 u1 = g_xh[(size_t)s1 * 32 + lane];
                float2 a0 = __half22float2(u32_as_h2(u0.x));
                float2 b0 = __half22float2(u32_as_h2(u0.y));
                float2 a1 = __half22float2(u32_as_h2(u1.x));
                float2 b1 = __half22float2(u32_as_h2(u1.y));
                acc.x += a0.x + a1.x; acc.y += a0.y + a1.y;
                acc.z += b0.x + b1.x; acc.w += b0.y + b1.y;
            }
            if (i < end) {
                int s0 = g_csr1[i];
                uint2 u0 = g_xh[(size_t)s0 * 32 + lane];
                float2 a0 = __half22float2(u32_as_h2(u0.x));
                float2 b0 = __half22float2(u32_as_h2(u0.y));
                acc.x += a0.x; acc.y += a0.y; acc.z += b0.x; acc.w += b0.y;
            }
            o.x = h2_as_u32(__floats2half2_rn(acc.x, acc.y));
            o.y = h2_as_u32(__floats2half2_rn(acc.z, acc.w));
        }
        Hs[r][64 + 2 * lane] = o.x;
        Hs[r][64 + 2 * lane + 1] = o.y;
    }

    // ---------------- Stage A: two 128x128 n-passes over W1 ----------------
#pragma unroll 1
    for (int pass = 0; pass < 2; pass++) {
        int cb = pass * 128;
        float c[2][8][4];
#pragma unroll
        for (int mi = 0; mi < 2; mi++)
#pragma unroll
            for (int ni = 0; ni < 8; ni++)
#pragma unroll
                for (int q = 0; q < 4; q++) c[mi][ni][q] = 0.f;

#pragma unroll 1
        for (int t = 0; t < 4; t++) {
            asm volatile("cp.async.wait_group 0;" ::: "memory");
            __syncthreads();   // tt=0: also publishes the gather writes
            int tt = pass * 4 + t;
            if (tt < 7) {
                int nt = tt + 1;
                loadB(g_w1h, FIN, (nt >= 4) ? 128 : 0, nt & 3, nt & 1);
            } else {
                loadB(g_w2h, FHID, 0, 0, 0);   // prefetch stage B tile 0
            }
            asm volatile("cp.async.commit_group;" ::: "memory");
            int buf = tt & 1;
#pragma unroll
            for (int kk2 = 0; kk2 < 16; kk2 += 8) {
                uint32_t af[2][4], bf[8][2];
#pragma unroll
                for (int mi = 0; mi < 2; mi++)
                    ldsm4(af[mi][0], af[mi][1], af[mi][2], af[mi][3],
                          smem_u32(&Hs[warp_m + mi * 16 + a_rowadd + lr]
                                      [64 + t * 16 + kk2 + a_kadd]));
#pragma unroll
                for (int p = 0; p < 4; p++)
                    ldsm4(bf[2 * p][0], bf[2 * p][1], bf[2 * p + 1][0], bf[2 * p + 1][1],
                          smem_u32(&Bst[buf][warp_n + p * 16 + b_nadd + lr][kk2 + b_kadd]));
#pragma unroll
                for (int mi = 0; mi < 2; mi++)
#pragma unroll
                    for (int ni = 0; ni < 8; ni++)
                        mma_f16(c[mi][ni], af[mi], bf[ni]);
            }
        }

        // Pass-1 epilogue overwrites the A region: wait for all warps' reads.
        if (pass == 1) __syncthreads();

        // Epilogue -> Hs fp16 (scale, bias, relu); rs1 = indeg1^-1/2 inline
#pragma unroll
        for (int mi = 0; mi < 2; mi++) {
#pragma unroll
            for (int half = 0; half < 2; half++) {
                int rl = warp_m + mi * 16 + g + half * 8;
                int row = rowBase + rl;
                float s = (row < M) ? inv_sqrt_cnt(g_icnt[OFF_IN1 + row]) : 0.f;
#pragma unroll
                for (int ni = 0; ni < 8; ni++) {
                    int col = cb + warp_n + ni * 8 + 2 * tig;
                    float v0 = 0.f, v1 = 0.f;
                    if (row < M) {
                        v0 = fmaxf(c[mi][ni][half * 2 + 0] * s + b1[col], 0.f);
                        v1 = fmaxf(c[mi][ni][half * 2 + 1] * s + b1[col + 1], 0.f);
                    }
                    Hs[rl][col >> 1] = h2_as_u32(__floats2half2_rn(v0, v1));
                }
            }
        }
    }

    // ---------------- Stage B: y = Hs @ W2 (K=256) -------------------------
    float c2[2][8][4];
#pragma unroll
    for (int mi = 0; mi < 2; mi++)
#pragma unroll
        for (int ni = 0; ni < 8; ni++)
#pragma unroll
            for (int q = 0; q < 4; q++) c2[mi][ni][q] = 0.f;

#pragma unroll 1
    for (int t = 0; t < 8; t++) {
        asm volatile("cp.async.wait_group 0;" ::: "memory");
        __syncthreads();   // t=0: also publishes the Hs epilogue writes
        if (t < 7) {
            loadB(g_w2h, FHID, 0, t + 1, (t + 1) & 1);
            asm volatile("cp.async.commit_group;" ::: "memory");
        }
        int buf = t & 1;
#pragma unroll
        for (int kk2 = 0; kk2 < 16; kk2 += 8) {
            uint32_t af[2][4], bf[8][2];
            int kb2 = t * 16 + kk2;
#pragma unroll
            for (int mi = 0; mi < 2; mi++)
                ldsm4(af[mi][0], af[mi][1], af[mi][2], af[mi][3],
                      smem_u32(&Hs[warp_m + mi * 16 + a_rowadd + lr][kb2 + a_kadd]));
#pragma unroll
            for (int p = 0; p < 4; p++)
                ldsm4(bf[2 * p][0], bf[2 * p][1], bf[2 * p + 1][0], bf[2 * p + 1][1],
                      smem_u32(&Bst[buf][warp_n + p * 16 + b_nadd + lr][kk2 + b_kadd]));
#pragma unroll
            for (int mi = 0; mi < 2; mi++)
#pragma unroll
                for (int ni = 0; ni < 8; ni++)
                    mma_f16(c2[mi][ni], af[mi], bf[ni]);
        }
    }

    // Epilogue -> Y (fp16, pre-scaled by outdeg2^-1/2 inline)
#pragma unroll
    for (int mi = 0; mi < 2; mi++) {
#pragma unroll
        for (int half = 0; half < 2; half++) {
            int row = rowBase + warp_m + mi * 16 + g + half * 8;
            if (row >= M) continue;
            float s = inv_sqrt_cnt(g_icnt[OFF_OUT2 + row]);
#pragma unroll
            for (int ni = 0; ni < 8; ni++) {
                int col = warp_n + ni * 8 + 2 * tig;
                __half2 h2 = __floats2half2_rn(c2[mi][ni][half * 2 + 0] * s,
                                               c2[mi][ni][half * 2 + 1] * s);
                *(__half2*)&Y[(size_t)row * FOUT + col] = h2;
            }
        }
    }
}

// ---------------------------------------------------------------------------
extern "C" void kernel_launch(void* const* d_in, const int* in_sizes, int n_in,
                              void* d_out, int out_size) {
    const float* x   = (const float*)d_in[0];
    const float* W1  = (const float*)d_in[1];
    const float* b1  = (const float*)d_in[2];
    const float* W2  = (const float*)d_in[3];
    const float* b2  = (const float*)d_in[4];
    const int* src1  = (const int*)d_in[5];
    const int* dst1  = (const int*)d_in[6];
    const int* src2  = (const int*)d_in[7];
    const int* dst2  = (const int*)d_in[8];
    float* out = (float*)d_out;

    __half* y16;
    cudaGetSymbolAddress((void**)&y16, g_y16);

    cudaFuncSetAttribute(fused_layer, cudaFuncAttributeMaxDynamicSharedMemorySize, SMEM_FUSED);

    const int TB = 256;

    // prep covers icnt zeroing (DEG_TOT/4) and weight transpose
    int prep_threads = (DEG_TOT / 4 > FIN * FHID) ? DEG_TOT / 4 : FIN * FHID;
    prep_kernel<<<(prep_threads + TB - 1) / TB, TB>>>(W1, W2);
    degree_kernel<<<(E1c + TB - 1) / TB, TB>>>(src1, dst1, src2, dst2);
    convscan_kernel<<<NBT + CVT_BLOCKS, 256>>>(x);
    scan_pass23<<<NBT, 256>>>();
    fill_kernel<<<(E1c + TB - 1) / TB, TB>>>(src1, dst1, src2, dst2);

    // Fused layer: CSR gather + h = fp16(relu(rs1*agg@W1+b1)) [smem]
    //              + y16 = fp16(rs2*(h@W2))
    fused_layer<<<(N1c + 127) / 128, 256, SMEM_FUSED>>>(y16, b1, N1c);

    // Layer 2 aggregate + fused scale/bias/relu -> out
    agg2_kernel<<<(N2c * 32 + TB - 1) / TB, TB>>>(b2, out);
}

// round 16
// speedup vs baseline: 1.2268x; 1.2268x over previous
#include <cuda_runtime.h>
#include <cuda_fp16.h>
#include <cstdint>
#include <cstddef>
#include <cstring>

// Problem constants (fixed-shape problem)
#define N0c 200000
#define N1c 100000
#define N2c 50000
#define E1c 1600000
#define E2c 800000
#define FIN 128
#define FHID 256
#define FOUT 128

// count layout: [0,N0) out1 | [N0,+N1) in1 | [+N1) out2 | [+N2) in2
#define OFF_OUT1 0
#define OFF_IN1  200000
#define OFF_OUT2 300000
#define OFF_IN2  400000
#define DEG_TOT  450000

#define NB1 ((N1c + 255) / 256)   // 391
#define NB2 ((N2c + 255) / 256)   // 196
#define NBT (NB1 + NB2)           // 587
#define CVT_BLOCKS ((N0c * 16 + 255) / 256)   // 12500

// Scratch (no allocations allowed)
__device__ int    g_icnt[DEG_TOT];
__device__ int    g_off1[N1c + 1];
__device__ int    g_cur1[N1c];
__device__ int    g_off2[N2c + 1];
__device__ int    g_cur2[N2c];
__device__ int    g_csr1[E1c];
__device__ int    g_csr2[E2c];
__device__ int    g_bsum[1024];
__device__ __half g_w1h[FHID * FIN];            // W1^T fp16 [n][k]
__device__ __half g_w2h[FOUT * FHID];           // W2^T fp16 [n][k]
__device__ uint2  g_xh[(size_t)N0c * 32];       // fp16 pre-scaled X, 51.2 MB
__device__ uint2  g_a16[(size_t)N1c * 32];      // fp16 agg1, 25.6 MB
__device__ __half g_y16[(size_t)N1c * FOUT];    // 25.6 MB

__device__ __forceinline__ uint32_t h2_as_u32(__half2 h) {
    uint32_t u; memcpy(&u, &h, 4); return u;
}
__device__ __forceinline__ __half2 u32_as_h2(uint32_t u) {
    __half2 h; memcpy(&h, &u, 4); return h;
}
__device__ __forceinline__ float inv_sqrt_cnt(int c) {
    return rsqrtf((float)max(c, 1));
}

// ---------------------------------------------------------------------------
__global__ void prep_kernel(const float* __restrict__ W1, const float* __restrict__ W2) {
    int i = blockIdx.x * blockDim.x + threadIdx.x;
    if (i < DEG_TOT / 4) ((int4*)g_icnt)[i] = make_int4(0, 0, 0, 0);
    if (i < DEG_TOT - (DEG_TOT / 4) * 4) g_icnt[(DEG_TOT / 4) * 4 + i] = 0;
    if (i < FIN * FHID) {                       // W1 [k=FIN][n=FHID] -> [n][k]
        int k = i / FHID, n = i % FHID;
        g_w1h[n * FIN + k] = __float2half(W1[i]);
    }
    if (i < FHID * FOUT) {                      // W2 [k=FHID][n=FOUT] -> [n][k]
        int k = i / FOUT, n = i % FOUT;
        g_w2h[n * FHID + k] = __float2half(W2[i]);
    }
}

__global__ void degree_kernel(const int* __restrict__ s1, const int* __restrict__ d1,
                              const int* __restrict__ s2, const int* __restrict__ d2) {
    int i = blockIdx.x * blockDim.x + threadIdx.x;
    if (i < E1c) {
        atomicAdd(&g_icnt[OFF_OUT1 + s1[i]], 1);
        atomicAdd(&g_icnt[OFF_IN1 + d1[i]], 1);
    }
    if (i < E2c) {
        atomicAdd(&g_icnt[OFF_OUT2 + s2[i]], 1);
        atomicAdd(&g_icnt[OFF_IN2 + d2[i]], 1);
    }
}

// Merged: blocks [0, NBT) = scan pass1; blocks [NBT, ...) = X -> fp16 convert.
__global__ __launch_bounds__(256) void convscan_kernel(const float* __restrict__ X) {
    int b = blockIdx.x, tid = threadIdx.x;
    if (b < NBT) {
        __shared__ int sh[256];
        int v = 0;
        if (b < NB1) {
            int idx = b * 256 + tid;
            if (idx < N1c) v = g_icnt[OFF_IN1 + idx];
        } else {
            int idx = (b - NB1) * 256 + tid;
            if (idx < N2c) v = g_icnt[OFF_IN2 + idx];
        }
        sh[tid] = v;
        __syncthreads();
        for (int s = 128; s > 0; s >>= 1) {
            if (tid < s) sh[tid] += sh[tid + s];
            __syncthreads();
        }
        if (tid == 0) g_bsum[b] = sh[0];
        return;
    }
    int i = (b - NBT) * 256 + tid;
    const int HALF = N0c * 16;
    if (i >= HALF) return;
#pragma unroll
    for (int j = 0; j < 2; j++) {
        int idx = i + j * HALF;
        int row = idx >> 5;
        float c = inv_sqrt_cnt(g_icnt[OFF_OUT1 + row]);
        float4 v = ((const float4*)X)[idx];
        uint2 o;
        o.x = h2_as_u32(__floats2half2_rn(v.x * c, v.y * c));
        o.y = h2_as_u32(__floats2half2_rn(v.z * c, v.w * c));
        g_xh[idx] = o;
    }
}

// Fused pass2+3: per-block prefix over g_bsum + local scan + CSR offsets.
__global__ __launch_bounds__(256) void scan_pass23() {
    __shared__ int sh[256];
    __shared__ int shr[256];
    int b = blockIdx.x, tid = threadIdx.x;
    bool g1 = (b < NB1);
    int seg_start = g1 ? 0 : NB1;

    int acc = 0;
    for (int p = seg_start + tid; p < b; p += 256) acc += g_bsum[p];
    shr[tid] = acc;
    __syncthreads();
    for (int s = 128; s > 0; s >>= 1) {
        if (tid < s) shr[tid] += shr[tid + s];
        __syncthreads();
    }
    int block_off = shr[0];

    int idx, v = 0;
    if (g1) {
        idx = b * 256 + tid;
        if (idx < N1c) v = g_icnt[OFF_IN1 + idx];
    } else {
        idx = (b - NB1) * 256 + tid;
        if (idx < N2c) v = g_icnt[OFF_IN2 + idx];
    }
    sh[tid] = v;
    __syncthreads();
    for (int s = 1; s < 256; s <<= 1) {
        int a = (tid >= s) ? sh[tid - s] : 0;
        __syncthreads();
        sh[tid] += a;
        __syncthreads();
    }
    int excl = block_off + sh[tid] - v;
    if (g1) {
        if (idx < N1c) { g_off1[idx] = excl; g_cur1[idx] = excl; }
    } else {
        if (idx < N2c) { g_off2[idx] = excl; g_cur2[idx] = excl; }
    }
    if (b == 0 && tid == 0) { g_off1[N1c] = E1c; g_off2[N2c] = E2c; }
}

// --- CSR fill (counting-sort edges by dst) ----------------------------------
__global__ void fill_kernel(const int* __restrict__ s1, const int* __restrict__ d1,
                            const int* __restrict__ s2, const int* __restrict__ d2) {
    int i = blockIdx.x * blockDim.x + threadIdx.x;
    if (i < E1c) {
        int p = atomicAdd(&g_cur1[d1[i]], 1);
        g_csr1[p] = s1[i];
    }
    if (i < E2c) {
        int p = atomicAdd(&g_cur2[d2[i]], 1);
        g_csr2[p] = s2[i];
    }
}

// --- Layer-1 aggregate: fp16 gather, fp32 accumulate, fp16 output -----------
__global__ __launch_bounds__(256) void agg1_kernel() {
    int w = (blockIdx.x * blockDim.x + threadIdx.x) >> 5;
    if (w >= N1c) return;
    int lane = threadIdx.x & 31;
    int i = g_off1[w], end = g_off1[w + 1];
    float4 acc = make_float4(0.f, 0.f, 0.f, 0.f);
    for (; i + 1 < end; i += 2) {
        int s0 = g_csr1[i], s1 = g_csr1[i + 1];
        uint2 u0 = g_xh[(size_t)s0 * 32 + lane];
        uint2 u1 = g_xh[(size_t)s1 * 32 + lane];
        float2 a0 = __half22float2(u32_as_h2(u0.x));
        float2 b0 = __half22float2(u32_as_h2(u0.y));
        float2 a1 = __half22float2(u32_as_h2(u1.x));
        float2 b1 = __half22float2(u32_as_h2(u1.y));
        acc.x += a0.x + a1.x; acc.y += a0.y + a1.y;
        acc.z += b0.x + b1.x; acc.w += b0.y + b1.y;
    }
    if (i < end) {
        int s0 = g_csr1[i];
        uint2 u0 = g_xh[(size_t)s0 * 32 + lane];
        float2 a0 = __half22float2(u32_as_h2(u0.x));
        float2 b0 = __half22float2(u32_as_h2(u0.y));
        acc.x += a0.x; acc.y += a0.y; acc.z += b0.x; acc.w += b0.y;
    }
    uint2 o;
    o.x = h2_as_u32(__floats2half2_rn(acc.x, acc.y));
    o.y = h2_as_u32(__floats2half2_rn(acc.z, acc.w));
    g_a16[(size_t)w * 32 + lane] = o;
}

// --- Layer-2 aggregate (fp16 gather) + fused scale/bias/relu ----------------
__global__ __launch_bounds__(256) void agg2_kernel(const float* __restrict__ bias,
                                                   float* __restrict__ OUT) {
    int w = (blockIdx.x * blockDim.x + threadIdx.x) >> 5;
    if (w >= N2c) return;
    int lane = threadIdx.x & 31;
    int i = g_off2[w], end = g_off2[w + 1];
    float4 acc = make_float4(0.f, 0.f, 0.f, 0.f);
    const uint2* Y2 = (const uint2*)g_y16;
    for (; i + 1 < end; i += 2) {
        int s0 = g_csr2[i], s1 = g_csr2[i + 1];
        uint2 u0 = Y2[(size_t)s0 * 32 + lane];
        uint2 u1 = Y2[(size_t)s1 * 32 + lane];
        float2 a0 = __half22float2(u32_as_h2(u0.x));
        float2 b0 = __half22float2(u32_as_h2(u0.y));
        float2 a1 = __half22float2(u32_as_h2(u1.x));
        float2 b1 = __half22float2(u32_as_h2(u1.y));
        acc.x += a0.x + a1.x; acc.y += a0.y + a1.y;
        acc.z += b0.x + b1.x; acc.w += b0.y + b1.y;
    }
    if (i < end) {
        int s0 = g_csr2[i];
        uint2 u0 = Y2[(size_t)s0 * 32 + lane];
        float2 a0 = __half22float2(u32_as_h2(u0.x));
        float2 b0 = __half22float2(u32_as_h2(u0.y));
        acc.x += a0.x; acc.y += a0.y; acc.z += b0.x; acc.w += b0.y;
    }
    float s = inv_sqrt_cnt(g_icnt[OFF_IN2 + w]);
    float4 b = ((const float4*)bias)[lane];
    acc.x = fmaxf(fmaf(acc.x, s, b.x), 0.f);
    acc.y = fmaxf(fmaf(acc.y, s, b.y), 0.f);
    acc.z = fmaxf(fmaf(acc.z, s, b.z), 0.f);
    acc.w = fmaxf(fmaf(acc.w, s, b.w), 0.f);
    ((float4*)OUT)[(size_t)w * 32 + lane] = acc;
}

// ---------------------------------------------------------------------------
// Fused fp16 MLP v2: A panel loaded ONCE into Hs upper half (cols 128..255
// region, dead until the pass-1 epilogue). Stage A waits only on L2-hot
// weight tiles. Continuous 8-tile B prefetch across both passes; stage B's
// first W2 tile prefetched during the last stage-A iteration.
// ---------------------------------------------------------------------------
#define TS 20                 // B tile row stride in uint32 (16 data + 4 pad)
#define HS2 132               // Hs row stride in uint32 (128 data + 4 pad)
#define BS_E (128 * TS)
#define HS_E (128 * HS2)
#define SMEM_FUSED ((HS_E + 2 * BS_E) * 4)

__device__ __forceinline__ uint32_t smem_u32(const void* p) {
    return (uint32_t)__cvta_generic_to_shared(p);
}
__device__ __forceinline__ void cp16(uint32_t dst, const void* src, int src_bytes) {
    asm volatile("cp.async.cg.shared.global [%0], [%1], 16, %2;"
                 :: "r"(dst), "l"(src), "r"(src_bytes));
}
__device__ __forceinline__ void mma_f16(float c[4], const uint32_t a[4], const uint32_t b[2]) {
    asm volatile(
        "mma.sync.aligned.m16n8k16.row.col.f32.f16.f16.f32 "
        "{%0,%1,%2,%3}, {%4,%5,%6,%7}, {%8,%9}, {%0,%1,%2,%3};"
        : "+f"(c[0]), "+f"(c[1]), "+f"(c[2]), "+f"(c[3])
        : "r"(a[0]), "r"(a[1]), "r"(a[2]), "r"(a[3]), "r"(b[0]), "r"(b[1]));
}
__device__ __forceinline__ void ldsm4(uint32_t& r0, uint32_t& r1, uint32_t& r2,
                                      uint32_t& r3, uint32_t addr) {
    asm volatile("ldmatrix.sync.aligned.m8n8.x4.shared.b16 {%0,%1,%2,%3}, [%4];"
                 : "=r"(r0), "=r"(r1), "=r"(r2), "=r"(r3) : "r"(addr));
}

__global__ __launch_bounds__(256) void fused_gemm(
    const __half* __restrict__ A16,   // agg1 [M,128] fp16
    __half* __restrict__ Y,           // [M,128] fp16
    const float* __restrict__ b1, int M)
{
    extern __shared__ uint32_t sm[];
    uint32_t (*Hs)[HS2]      = (uint32_t (*)[HS2])sm;
    uint32_t (*Bst)[128][TS] = (uint32_t (*)[128][TS])(sm + HS_E);

    int tid = threadIdx.x;
    int wid = tid >> 5, lane = tid & 31;
    int g = lane >> 2, tig = lane & 3;
    int warp_m = (wid & 3) * 32;
    int warp_n = (wid >> 2) * 64;
    int rowBase = blockIdx.x * 128;

    // ldmatrix source indexing
    int j = lane >> 3, lr = lane & 7;
    int a_rowadd = (j & 1) * 8;
    int a_kadd   = (j >> 1) * 4;
    int b_nadd   = (j >> 1) * 8;
    int b_kadd   = (j & 1) * 4;

    auto loadB = [&](const __half* Wt, int ldk, int nb, int t, int buf) {
#pragma unroll
        for (int i = 0; i < 2; i++) {
            int gI = tid + 256 * i;
            int brow = gI >> 2, b16 = gI & 3;
            cp16(smem_u32(&Bst[buf][brow][b16 * 4]),
                 Wt + ((size_t)(nb + brow) * ldk + t * 32 + b16 * 8), 16);
        }
    };

    // Prologue: full A panel (128 rows x 128 halfs) into Hs[.][64..127],
    // 16 x 16B chunks per row, 8 chunks per thread.
#pragma unroll
    for (int i = 0; i < 8; i++) {
        int gI = tid + 256 * i;
        int arow = gI >> 4, ac = gI & 15;
        int gr = rowBase + arow;
        cp16(smem_u32(&Hs[arow][64 + ac * 4]),
             A16 + ((size_t)(gr < M ? gr : 0) * FIN + ac * 8), gr < M ? 16 : 0);
    }
    loadB(g_w1h, FIN, 0, 0, 0);
    asm volatile("cp.async.commit_group;" ::: "memory");

    // ---------------- Stage A: two 128x128 n-passes over W1 ----------------
#pragma unroll 1
    for (int pass = 0; pass < 2; pass++) {
        int cb = pass * 128;
        float c[2][8][4];
#pragma unroll
        for (int mi = 0; mi < 2; mi++)
#pragma unroll
            for (int ni = 0; ni < 8; ni++)
#pragma unroll
                for (int q = 0; q < 4; q++) c[mi][ni][q] = 0.f;

#pragma unroll 1
        for (int t = 0; t < 4; t++) {
            asm volatile("cp.async.wait_group 0;" ::: "memory");
            __syncthreads();
            int tt = pass * 4 + t;
            if (tt < 7) {
                int nt = tt + 1;
                loadB(g_w1h, FIN, (nt >= 4) ? 128 : 0, nt & 3, nt & 1);
            } else {
                loadB(g_w2h, FHID, 0, 0, 0);   // prefetch stage B tile 0
            }
            asm volatile("cp.async.commit_group;" ::: "memory");
            int buf = tt & 1;
#pragma unroll
            for (int kk2 = 0; kk2 < 16; kk2 += 8) {
                uint32_t af[2][4], bf[8][2];
#pragma unroll
                for (int mi = 0; mi < 2; mi++)
                    ldsm4(af[mi][0], af[mi][1], af[mi][2], af[mi][3],
                          smem_u32(&Hs[warp_m + mi * 16 + a_rowadd + lr]
                                      [64 + t * 16 + kk2 + a_kadd]));
#pragma unroll
                for (int p = 0; p < 4; p++)
                    ldsm4(bf[2 * p][0], bf[2 * p][1], bf[2 * p + 1][0], bf[2 * p + 1][1],
                          smem_u32(&Bst[buf][warp_n + p * 16 + b_nadd + lr][kk2 + b_kadd]));
#pragma unroll
                for (int mi = 0; mi < 2; mi++)
#pragma unroll
                    for (int ni = 0; ni < 8; ni++)
                        mma_f16(c[mi][ni], af[mi], bf[ni]);
            }
        }

        // Pass-1 epilogue overwrites the A region: wait for all warps' reads.
        if (pass == 1) __syncthreads();

        // Epilogue -> Hs fp16 (scale, bias, relu); rs1 = indeg1^-1/2 inline
#pragma unroll
        for (int mi = 0; mi < 2; mi++) {
#pragma unroll
            for (int half = 0; half < 2; half++) {
                int rl = warp_m + mi * 16 + g + half * 8;
                int row = rowBase + rl;
                float s = (row < M) ? inv_sqrt_cnt(g_icnt[OFF_IN1 + row]) : 0.f;
#pragma unroll
                for (int ni = 0; ni < 8; ni++) {
                    int col = cb + warp_n + ni * 8 + 2 * tig;
                    float v0 = 0.f, v1 = 0.f;
                    if (row < M) {
                        v0 = fmaxf(c[mi][ni][half * 2 + 0] * s + b1[col], 0.f);
                        v1 = fmaxf(c[mi][ni][half * 2 + 1] * s + b1[col + 1], 0.f);
                    }
                    Hs[rl][col >> 1] = h2_as_u32(__floats2half2_rn(v0, v1));
                }
            }
        }
    }

    // ---------------- Stage B: y = Hs @ W2 (K=256) -------------------------
    float c2[2][8][4];
#pragma unroll
    for (int mi = 0; mi < 2; mi++)
#pragma unroll
        for (int ni = 0; ni < 8; ni++)
#pragma unroll
            for (int q = 0; q < 4; q++) c2[mi][ni][q] = 0.f;

#pragma unroll 1
    for (int t = 0; t < 8; t++) {
        asm volatile("cp.async.wait_group 0;" ::: "memory");
        __syncthreads();   // t=0: also publishes the Hs epilogue writes
        if (t < 7) {
            loadB(g_w2h, FHID, 0, t + 1, (t + 1) & 1);
            asm volatile("cp.async.commit_group;" ::: "memory");
        }
        int buf = t & 1;
#pragma unroll
        for (int kk2 = 0; kk2 < 16; kk2 += 8) {
            uint32_t af[2][4], bf[8][2];
            int kb2 = t * 16 + kk2;
#pragma unroll
            for (int mi = 0; mi < 2; mi++)
                ldsm4(af[mi][0], af[mi][1], af[mi][2], af[mi][3],
                      smem_u32(&Hs[warp_m + mi * 16 + a_rowadd + lr][kb2 + a_kadd]));
#pragma unroll
            for (int p = 0; p < 4; p++)
                ldsm4(bf[2 * p][0], bf[2 * p][1], bf[2 * p + 1][0], bf[2 * p + 1][1],
                      smem_u32(&Bst[buf][warp_n + p * 16 + b_nadd + lr][kk2 + b_kadd]));
#pragma unroll
            for (int mi = 0; mi < 2; mi++)
#pragma unroll
                for (int ni = 0; ni < 8; ni++)
                    mma_f16(c2[mi][ni], af[mi], bf[ni]);
        }
    }

    // Epilogue -> Y (fp16, pre-scaled by outdeg2^-1/2 inline)
#pragma unroll
    for (int mi = 0; mi < 2; mi++) {
#pragma unroll
        for (int half = 0; half < 2; half++) {
            int row = rowBase + warp_m + mi * 16 + g + half * 8;
            if (row >= M) continue;
            float s = inv_sqrt_cnt(g_icnt[OFF_OUT2 + row]);
#pragma unroll
            for (int ni = 0; ni < 8; ni++) {
                int col = warp_n + ni * 8 + 2 * tig;
                __half2 h2 = __floats2half2_rn(c2[mi][ni][half * 2 + 0] * s,
                                               c2[mi][ni][half * 2 + 1] * s);
                *(__half2*)&Y[(size_t)row * FOUT + col] = h2;
            }
        }
    }
}

// ---------------------------------------------------------------------------
extern "C" void kernel_launch(void* const* d_in, const int* in_sizes, int n_in,
                              void* d_out, int out_size) {
    const float* x   = (const float*)d_in[0];
    const float* W1  = (const float*)d_in[1];
    const float* b1  = (const float*)d_in[2];
    const float* W2  = (const float*)d_in[3];
    const float* b2  = (const float*)d_in[4];
    const int* src1  = (const int*)d_in[5];
    const int* dst1  = (const int*)d_in[6];
    const int* src2  = (const int*)d_in[7];
    const int* dst2  = (const int*)d_in[8];
    float* out = (float*)d_out;

    __half *a16, *y16;
    cudaGetSymbolAddress((void**)&a16, g_a16);
    cudaGetSymbolAddress((void**)&y16, g_y16);

    cudaFuncSetAttribute(fused_gemm, cudaFuncAttributeMaxDynamicSharedMemorySize, SMEM_FUSED);

    const int TB = 256;

    // prep covers icnt zeroing (DEG_TOT/4) and weight transpose
    int prep_threads = (DEG_TOT / 4 > FIN * FHID) ? DEG_TOT / 4 : FIN * FHID;
    prep_kernel<<<(prep_threads + TB - 1) / TB, TB>>>(W1, W2);
    degree_kernel<<<(E1c + TB - 1) / TB, TB>>>(src1, dst1, src2, dst2);
    convscan_kernel<<<NBT + CVT_BLOCKS, 256>>>(x);
    scan_pass23<<<NBT, 256>>>();
    fill_kernel<<<(E1c + TB - 1) / TB, TB>>>(src1, dst1, src2, dst2);

    // Layer 1 aggregate (fp16 gather): a16 = fp16( segsum(xh) )
    agg1_kernel<<<(N1c * 32 + TB - 1) / TB, TB>>>();

    // Fused: h = fp16(relu(rs1*a16@W1+b1)) [smem]; y16 = fp16(rs2*(h@W2))
    fused_gemm<<<(N1c + 127) / 128, 256, SMEM_FUSED>>>(a16, y16, b1, N1c);

    // Layer 2 aggregate + fused scale/bias/relu -> out
    agg2_kernel<<<(N2c * 32 + TB - 1) / TB, TB>>>(b2, out);
}